// round 11
// baseline (speedup 1.0000x reference)
#include <cuda_runtime.h>
#include <math.h>

// ---------------------------------------------------------------------------
// TensoRF shading, round 2: packed-f32x2 (FFMA2) MLP + sincos double-angle
// recurrence. Per block: 32 samples. Encoded input stored TRANSPOSED in SMEM
// (row = channel, col = sample) with a pair-swizzle so that:
//   - GEMM reads are LDS.64 broadcasts (all lanes of a warp share a sample grp)
//   - epilogue STS.64 writes land exactly 2 lanes per bank-pair (free)
// Thread tile: 4 output features x 4 samples = 8 f32x2 accumulators.
// ---------------------------------------------------------------------------

#define NRAYS 4096
#define NS    128
#define NSAMP (NRAYS * NS)
#define APPD  27
#define INC   390
#define FC    128
#define STILE 32
#define THREADS 256

// col slot for (row r, sample s) in a transposed 32-wide tile
#define XCOL(r, s) ((((((s) >> 1) + ((r) >> 2)) & 15) << 1) + ((s) & 1))

static __device__ float g_rgb[(size_t)NSAMP * 3];

__device__ __forceinline__ unsigned long long pk2(float a, float b) {
    unsigned long long r;
    asm("mov.b64 %0, {%1, %2};" : "=l"(r)
        : "r"(__float_as_uint(a)), "r"(__float_as_uint(b)));
    return r;
}
__device__ __forceinline__ void upk2(unsigned long long p, float& a, float& b) {
    unsigned int x, y;
    asm("mov.b64 {%0, %1}, %2;" : "=r"(x), "=r"(y) : "l"(p));
    a = __uint_as_float(x); b = __uint_as_float(y);
}
__device__ __forceinline__ unsigned long long ffma2(
    unsigned long long a, unsigned long long b, unsigned long long c) {
    unsigned long long d;
    asm("fma.rn.f32x2 %0, %1, %2, %3;" : "=l"(d) : "l"(a), "l"(b), "l"(c));
    return d;
}

// one 4-column step of the register-tiled GEMM
__device__ __forceinline__ void gemm_step(
    const float* __restrict__ xs, const float4* __restrict__ wp,
    int c, int colA, int colB,
    unsigned long long a01[4], unsigned long long a23[4])
{
    unsigned long long x01 = *(const unsigned long long*)(xs + c * 32 + colA);
    unsigned long long x23 = *(const unsigned long long*)(xs + c * 32 + colB);
    float4 w = wp[c * 32];
    unsigned long long w0 = pk2(w.x, w.x);
    unsigned long long w1 = pk2(w.y, w.y);
    unsigned long long w2 = pk2(w.z, w.z);
    unsigned long long w3 = pk2(w.w, w.w);
    a01[0] = ffma2(x01, w0, a01[0]);  a23[0] = ffma2(x23, w0, a23[0]);
    a01[1] = ffma2(x01, w1, a01[1]);  a23[1] = ffma2(x23, w1, a23[1]);
    a01[2] = ffma2(x01, w2, a01[2]);  a23[2] = ffma2(x23, w2, a23[2]);
    a01[3] = ffma2(x01, w3, a01[3]);  a23[3] = ffma2(x23, w3, a23[3]);
}

__device__ __forceinline__ void gemm_epilogue(
    float* __restrict__ dst, const float* __restrict__ bias,
    int fg, int sh,
    unsigned long long a01[4], unsigned long long a23[4])
{
    const float4 bb = *((const float4*)bias + fg);
    const float bf[4] = {bb.x, bb.y, bb.z, bb.w};
    const int colAw = ((sh + fg) & 15) << 1;
    const int colBw = ((sh + 1 + fg) & 15) << 1;
    #pragma unroll
    for (int f = 0; f < 4; f++) {
        int r = 4 * fg + f;
        float v0, v1, v2, v3;
        upk2(a01[f], v0, v1);
        upk2(a23[f], v2, v3);
        v0 = fmaxf(v0 + bf[f], 0.f);
        v1 = fmaxf(v1 + bf[f], 0.f);
        v2 = fmaxf(v2 + bf[f], 0.f);
        v3 = fmaxf(v3 + bf[f], 0.f);
        *(unsigned long long*)(dst + r * 32 + colAw) = pk2(v0, v1);
        *(unsigned long long*)(dst + r * 32 + colBw) = pk2(v2, v3);
    }
}

__global__ void __launch_bounds__(THREADS) mlp_kernel(
    const float* __restrict__ app,
    const float* __restrict__ view,
    const float* __restrict__ W1, const float* __restrict__ b1,
    const float* __restrict__ W2, const float* __restrict__ b2,
    const float* __restrict__ W3, const float* __restrict__ b3)
{
    extern __shared__ __align__(16) float smem[];
    float* xs  = smem;            // [392][32] encoded input (transposed), 390 rows used
    float* h1  = xs + 392 * 32;   // [128][32]
    float* h2  = h1 + 128 * 32;   // [128][32]
    float* w3s = h2 + 128 * 32;   // [384]
    float* b3s = w3s + 384;       // [4]

    const int tid = threadIdx.x;
    const size_t base = (size_t)blockIdx.x * STILE;

    // ---- stage W3/b3 ----
    w3s[tid] = W3[tid & 255 ? tid : tid];  // plain copy below
    w3s[tid] = W3[tid];
    if (tid < 128) w3s[256 + tid] = W3[256 + tid];
    if (tid < 3)   b3s[tid] = b3[tid];

    // ---- build encoded input (transposed, pair-swizzled) ----
    // rows: [0:27) app | [27:30) view | [30:192) sin(PE app) | [192:354) cos
    //       | [354:372) sin(PE view) | [372:390) cos(PE view)
    {
        const int s = tid >> 3;   // 0..31
        const int j = tid & 7;
        const size_t gs = base + s;
        const float* af = app + gs * APPD;
        #pragma unroll
        for (int cc = 0; cc < 4; cc++) {
            int c = j + cc * 8;
            if (c < APPD) {
                float v = af[c];
                xs[c * 32 + XCOL(c, s)] = v;
                float sn, cs;
                __sincosf(v, &sn, &cs);
                int rs = 30 + c * 6, rc = 192 + c * 6;
                #pragma unroll
                for (int f = 0; f < 6; f++) {
                    xs[(rs + f) * 32 + XCOL(rs + f, s)] = sn;
                    xs[(rc + f) * 32 + XCOL(rc + f, s)] = cs;
                    float sn2 = 2.f * sn * cs;        // double-angle recurrence
                    float cs2 = 1.f - 2.f * sn * sn;
                    sn = sn2; cs = cs2;
                }
            }
        }
        if (j < 3) {
            float v = view[gs * 3 + j];
            xs[(27 + j) * 32 + XCOL(27 + j, s)] = v;
            float sn, cs;
            __sincosf(v, &sn, &cs);
            int rs = 354 + j * 6, rc = 372 + j * 6;
            #pragma unroll
            for (int f = 0; f < 6; f++) {
                xs[(rs + f) * 32 + XCOL(rs + f, s)] = sn;
                xs[(rc + f) * 32 + XCOL(rc + f, s)] = cs;
                float sn2 = 2.f * sn * cs;
                float cs2 = 1.f - 2.f * sn * sn;
                sn = sn2; cs = cs2;
            }
        }
    }
    __syncthreads();

    const int fg = tid & 31;        // feature group: outputs 4fg..4fg+3
    const int sg = tid >> 5;        // sample group (warp): samples 4sg..4sg+3
    const int s0 = 4 * sg;
    const int sh = s0 >> 1;

    unsigned long long a01[4], a23[4];

    // ---- layer 1: [32,390] x [390,128] ----
    #pragma unroll
    for (int f = 0; f < 4; f++) { a01[f] = 0ull; a23[f] = 0ull; }
    {
        const float4* wp = (const float4*)W1 + fg;
        for (int cb = 0; cb < 388; cb += 4) {
            int cb4 = cb >> 2;
            int colA = (((sh + cb4) & 15) << 1);
            int colB = (((sh + 1 + cb4) & 15) << 1);
            #pragma unroll
            for (int u = 0; u < 4; u++)
                gemm_step(xs, wp, cb + u, colA, colB, a01, a23);
        }
        {   // remainder c = 388, 389 (same c>>2 = 97 group)
            int colA = (((sh + 97) & 15) << 1);
            int colB = (((sh + 1 + 97) & 15) << 1);
            gemm_step(xs, wp, 388, colA, colB, a01, a23);
            gemm_step(xs, wp, 389, colA, colB, a01, a23);
        }
        gemm_epilogue(h1, b1, fg, sh, a01, a23);
    }
    __syncthreads();

    // ---- layer 2: [32,128] x [128,128] ----
    #pragma unroll
    for (int f = 0; f < 4; f++) { a01[f] = 0ull; a23[f] = 0ull; }
    {
        const float4* wp = (const float4*)W2 + fg;
        for (int cb = 0; cb < FC; cb += 4) {
            int cb4 = cb >> 2;
            int colA = (((sh + cb4) & 15) << 1);
            int colB = (((sh + 1 + cb4) & 15) << 1);
            #pragma unroll
            for (int u = 0; u < 4; u++)
                gemm_step(h1, wp, cb + u, colA, colB, a01, a23);
        }
        gemm_epilogue(h2, b2, fg, sh, a01, a23);
    }
    __syncthreads();

    // ---- layer 3: [32,128] x [128,3] + sigmoid ----
    if (tid < 96) {
        const int s = tid / 3;
        const int o = tid - 3 * s;
        float sum = b3s[o];
        #pragma unroll 8
        for (int g = 0; g < FC; g++) {
            float hv = h2[g * 32 + XCOL(g, s)];
            sum = fmaf(hv, w3s[g * 3 + o], sum);
        }
        g_rgb[(base + s) * 3 + o] = 1.0f / (1.0f + expf(-sum));
    }
}

// ---------------------------------------------------------------------------
// Per-ray composite (unchanged math, better SM spread: 128 blocks of 32)
// ---------------------------------------------------------------------------
__global__ void __launch_bounds__(32) reduce_kernel(
    const float* __restrict__ sf,
    const float* __restrict__ dd,
    float* __restrict__ out)
{
    const int r = blockIdx.x * blockDim.x + threadIdx.x;
    if (r >= NRAYS) return;

    const float* s  = sf + (size_t)r * NS;
    const float* d  = dd + (size_t)r * NS;
    const float* rb = g_rgb + (size_t)r * NS * 3;

    float T = 1.0f, o0 = 0.0f, o1 = 0.0f, o2 = 0.0f;
    #pragma unroll 4
    for (int i = 0; i < NS; i++) {
        float x = s[i] - 10.0f;
        float sig = log1pf(expf(x));
        float alpha = (i == NS - 1) ? 1.0f
                    : (1.0f - expf(-sig * d[i] * 25.0f));
        float w = alpha * T;
        o0 = fmaf(w, rb[i * 3 + 0], o0);
        o1 = fmaf(w, rb[i * 3 + 1], o1);
        o2 = fmaf(w, rb[i * 3 + 2], o2);
        T *= (1.0f - alpha + 1e-10f);
    }
    out[r * 3 + 0] = o0;
    out[r * 3 + 1] = o1;
    out[r * 3 + 2] = o2;
}

// ---------------------------------------------------------------------------
extern "C" void kernel_launch(void* const* d_in, const int* in_sizes, int n_in,
                              void* d_out, int out_size)
{
    const float* sigma = (const float*)d_in[0];
    const float* app   = (const float*)d_in[1];
    const float* view  = (const float*)d_in[2];
    const float* dists = (const float*)d_in[3];
    const float* W1    = (const float*)d_in[4];
    const float* b1    = (const float*)d_in[5];
    const float* W2    = (const float*)d_in[6];
    const float* b2    = (const float*)d_in[7];
    const float* W3    = (const float*)d_in[8];
    const float* b3    = (const float*)d_in[9];
    float* out = (float*)d_out;

    const int smem_bytes = (392 * 32 + 128 * 32 + 128 * 32 + 384 + 4) * 4;
    cudaFuncSetAttribute(mlp_kernel,
                         cudaFuncAttributeMaxDynamicSharedMemorySize, smem_bytes);

    mlp_kernel<<<NSAMP / STILE, THREADS, smem_bytes>>>(
        app, view, W1, b1, W2, b2, W3, b3);
    reduce_kernel<<<NRAYS / 32, 32>>>(sigma, dists, out);
}

// round 12
// speedup vs baseline: 1.0032x; 1.0032x over previous
#include <cuda_runtime.h>
#include <math.h>

// ---------------------------------------------------------------------------
// TensoRF shading, round 2: packed-f32x2 (FFMA2) MLP + sincos double-angle
// recurrence. Per block: 32 samples. Encoded input stored TRANSPOSED in SMEM
// (row = channel, col = sample) with a pair-swizzle so that:
//   - GEMM reads are LDS.64 broadcasts (all lanes of a warp share a sample grp)
//   - epilogue STS.64 writes land exactly 2 lanes per bank-pair (free)
// Thread tile: 4 output features x 4 samples = 8 f32x2 accumulators.
// ---------------------------------------------------------------------------

#define NRAYS 4096
#define NS    128
#define NSAMP (NRAYS * NS)
#define APPD  27
#define INC   390
#define FC    128
#define STILE 32
#define THREADS 256

// col slot for (row r, sample s) in a transposed 32-wide tile
#define XCOL(r, s) ((((((s) >> 1) + ((r) >> 2)) & 15) << 1) + ((s) & 1))

static __device__ float g_rgb[(size_t)NSAMP * 3];

__device__ __forceinline__ unsigned long long pk2(float a, float b) {
    unsigned long long r;
    asm("mov.b64 %0, {%1, %2};" : "=l"(r)
        : "r"(__float_as_uint(a)), "r"(__float_as_uint(b)));
    return r;
}
__device__ __forceinline__ void upk2(unsigned long long p, float& a, float& b) {
    unsigned int x, y;
    asm("mov.b64 {%0, %1}, %2;" : "=r"(x), "=r"(y) : "l"(p));
    a = __uint_as_float(x); b = __uint_as_float(y);
}
__device__ __forceinline__ unsigned long long ffma2(
    unsigned long long a, unsigned long long b, unsigned long long c) {
    unsigned long long d;
    asm("fma.rn.f32x2 %0, %1, %2, %3;" : "=l"(d) : "l"(a), "l"(b), "l"(c));
    return d;
}

// one 4-column step of the register-tiled GEMM
__device__ __forceinline__ void gemm_step(
    const float* __restrict__ xs, const float4* __restrict__ wp,
    int c, int colA, int colB,
    unsigned long long a01[4], unsigned long long a23[4])
{
    unsigned long long x01 = *(const unsigned long long*)(xs + c * 32 + colA);
    unsigned long long x23 = *(const unsigned long long*)(xs + c * 32 + colB);
    float4 w = wp[c * 32];
    unsigned long long w0 = pk2(w.x, w.x);
    unsigned long long w1 = pk2(w.y, w.y);
    unsigned long long w2 = pk2(w.z, w.z);
    unsigned long long w3 = pk2(w.w, w.w);
    a01[0] = ffma2(x01, w0, a01[0]);  a23[0] = ffma2(x23, w0, a23[0]);
    a01[1] = ffma2(x01, w1, a01[1]);  a23[1] = ffma2(x23, w1, a23[1]);
    a01[2] = ffma2(x01, w2, a01[2]);  a23[2] = ffma2(x23, w2, a23[2]);
    a01[3] = ffma2(x01, w3, a01[3]);  a23[3] = ffma2(x23, w3, a23[3]);
}

__device__ __forceinline__ void gemm_epilogue(
    float* __restrict__ dst, const float* __restrict__ bias,
    int fg, int sh,
    unsigned long long a01[4], unsigned long long a23[4])
{
    const float4 bb = *((const float4*)bias + fg);
    const float bf[4] = {bb.x, bb.y, bb.z, bb.w};
    const int colAw = ((sh + fg) & 15) << 1;
    const int colBw = ((sh + 1 + fg) & 15) << 1;
    #pragma unroll
    for (int f = 0; f < 4; f++) {
        int r = 4 * fg + f;
        float v0, v1, v2, v3;
        upk2(a01[f], v0, v1);
        upk2(a23[f], v2, v3);
        v0 = fmaxf(v0 + bf[f], 0.f);
        v1 = fmaxf(v1 + bf[f], 0.f);
        v2 = fmaxf(v2 + bf[f], 0.f);
        v3 = fmaxf(v3 + bf[f], 0.f);
        *(unsigned long long*)(dst + r * 32 + colAw) = pk2(v0, v1);
        *(unsigned long long*)(dst + r * 32 + colBw) = pk2(v2, v3);
    }
}

__global__ void __launch_bounds__(THREADS) mlp_kernel(
    const float* __restrict__ app,
    const float* __restrict__ view,
    const float* __restrict__ W1, const float* __restrict__ b1,
    const float* __restrict__ W2, const float* __restrict__ b2,
    const float* __restrict__ W3, const float* __restrict__ b3)
{
    extern __shared__ __align__(16) float smem[];
    float* xs  = smem;            // [392][32] encoded input (transposed), 390 rows used
    float* h1  = xs + 392 * 32;   // [128][32]
    float* h2  = h1 + 128 * 32;   // [128][32]
    float* w3s = h2 + 128 * 32;   // [384]
    float* b3s = w3s + 384;       // [4]

    const int tid = threadIdx.x;
    const size_t base = (size_t)blockIdx.x * STILE;

    // ---- stage W3/b3 ----
    w3s[tid] = W3[tid & 255 ? tid : tid];  // plain copy below
    w3s[tid] = W3[tid];
    if (tid < 128) w3s[256 + tid] = W3[256 + tid];
    if (tid < 3)   b3s[tid] = b3[tid];

    // ---- build encoded input (transposed, pair-swizzled) ----
    // rows: [0:27) app | [27:30) view | [30:192) sin(PE app) | [192:354) cos
    //       | [354:372) sin(PE view) | [372:390) cos(PE view)
    {
        const int s = tid >> 3;   // 0..31
        const int j = tid & 7;
        const size_t gs = base + s;
        const float* af = app + gs * APPD;
        #pragma unroll
        for (int cc = 0; cc < 4; cc++) {
            int c = j + cc * 8;
            if (c < APPD) {
                float v = af[c];
                xs[c * 32 + XCOL(c, s)] = v;
                float sn, cs;
                __sincosf(v, &sn, &cs);
                int rs = 30 + c * 6, rc = 192 + c * 6;
                #pragma unroll
                for (int f = 0; f < 6; f++) {
                    xs[(rs + f) * 32 + XCOL(rs + f, s)] = sn;
                    xs[(rc + f) * 32 + XCOL(rc + f, s)] = cs;
                    float sn2 = 2.f * sn * cs;        // double-angle recurrence
                    float cs2 = 1.f - 2.f * sn * sn;
                    sn = sn2; cs = cs2;
                }
            }
        }
        if (j < 3) {
            float v = view[gs * 3 + j];
            xs[(27 + j) * 32 + XCOL(27 + j, s)] = v;
            float sn, cs;
            __sincosf(v, &sn, &cs);
            int rs = 354 + j * 6, rc = 372 + j * 6;
            #pragma unroll
            for (int f = 0; f < 6; f++) {
                xs[(rs + f) * 32 + XCOL(rs + f, s)] = sn;
                xs[(rc + f) * 32 + XCOL(rc + f, s)] = cs;
                float sn2 = 2.f * sn * cs;
                float cs2 = 1.f - 2.f * sn * sn;
                sn = sn2; cs = cs2;
            }
        }
    }
    __syncthreads();

    const int fg = tid & 31;        // feature group: outputs 4fg..4fg+3
    const int sg = tid >> 5;        // sample group (warp): samples 4sg..4sg+3
    const int s0 = 4 * sg;
    const int sh = s0 >> 1;

    unsigned long long a01[4], a23[4];

    // ---- layer 1: [32,390] x [390,128] ----
    #pragma unroll
    for (int f = 0; f < 4; f++) { a01[f] = 0ull; a23[f] = 0ull; }
    {
        const float4* wp = (const float4*)W1 + fg;
        for (int cb = 0; cb < 388; cb += 4) {
            int cb4 = cb >> 2;
            int colA = (((sh + cb4) & 15) << 1);
            int colB = (((sh + 1 + cb4) & 15) << 1);
            #pragma unroll
            for (int u = 0; u < 4; u++)
                gemm_step(xs, wp, cb + u, colA, colB, a01, a23);
        }
        {   // remainder c = 388, 389 (same c>>2 = 97 group)
            int colA = (((sh + 97) & 15) << 1);
            int colB = (((sh + 1 + 97) & 15) << 1);
            gemm_step(xs, wp, 388, colA, colB, a01, a23);
            gemm_step(xs, wp, 389, colA, colB, a01, a23);
        }
        gemm_epilogue(h1, b1, fg, sh, a01, a23);
    }
    __syncthreads();

    // ---- layer 2: [32,128] x [128,128] ----
    #pragma unroll
    for (int f = 0; f < 4; f++) { a01[f] = 0ull; a23[f] = 0ull; }
    {
        const float4* wp = (const float4*)W2 + fg;
        for (int cb = 0; cb < FC; cb += 4) {
            int cb4 = cb >> 2;
            int colA = (((sh + cb4) & 15) << 1);
            int colB = (((sh + 1 + cb4) & 15) << 1);
            #pragma unroll
            for (int u = 0; u < 4; u++)
                gemm_step(h1, wp, cb + u, colA, colB, a01, a23);
        }
        gemm_epilogue(h2, b2, fg, sh, a01, a23);
    }
    __syncthreads();

    // ---- layer 3: [32,128] x [128,3] + sigmoid ----
    if (tid < 96) {
        const int s = tid / 3;
        const int o = tid - 3 * s;
        float sum = b3s[o];
        #pragma unroll 8
        for (int g = 0; g < FC; g++) {
            float hv = h2[g * 32 + XCOL(g, s)];
            sum = fmaf(hv, w3s[g * 3 + o], sum);
        }
        g_rgb[(base + s) * 3 + o] = 1.0f / (1.0f + expf(-sum));
    }
}

// ---------------------------------------------------------------------------
// Per-ray composite (unchanged math, better SM spread: 128 blocks of 32)
// ---------------------------------------------------------------------------
__global__ void __launch_bounds__(32) reduce_kernel(
    const float* __restrict__ sf,
    const float* __restrict__ dd,
    float* __restrict__ out)
{
    const int r = blockIdx.x * blockDim.x + threadIdx.x;
    if (r >= NRAYS) return;

    const float* s  = sf + (size_t)r * NS;
    const float* d  = dd + (size_t)r * NS;
    const float* rb = g_rgb + (size_t)r * NS * 3;

    float T = 1.0f, o0 = 0.0f, o1 = 0.0f, o2 = 0.0f;
    #pragma unroll 4
    for (int i = 0; i < NS; i++) {
        float x = s[i] - 10.0f;
        float sig = log1pf(expf(x));
        float alpha = (i == NS - 1) ? 1.0f
                    : (1.0f - expf(-sig * d[i] * 25.0f));
        float w = alpha * T;
        o0 = fmaf(w, rb[i * 3 + 0], o0);
        o1 = fmaf(w, rb[i * 3 + 1], o1);
        o2 = fmaf(w, rb[i * 3 + 2], o2);
        T *= (1.0f - alpha + 1e-10f);
    }
    out[r * 3 + 0] = o0;
    out[r * 3 + 1] = o1;
    out[r * 3 + 2] = o2;
}

// ---------------------------------------------------------------------------
extern "C" void kernel_launch(void* const* d_in, const int* in_sizes, int n_in,
                              void* d_out, int out_size)
{
    const float* sigma = (const float*)d_in[0];
    const float* app   = (const float*)d_in[1];
    const float* view  = (const float*)d_in[2];
    const float* dists = (const float*)d_in[3];
    const float* W1    = (const float*)d_in[4];
    const float* b1    = (const float*)d_in[5];
    const float* W2    = (const float*)d_in[6];
    const float* b2    = (const float*)d_in[7];
    const float* W3    = (const float*)d_in[8];
    const float* b3    = (const float*)d_in[9];
    float* out = (float*)d_out;

    const int smem_bytes = (392 * 32 + 128 * 32 + 128 * 32 + 384 + 4) * 4;
    cudaFuncSetAttribute(mlp_kernel,
                         cudaFuncAttributeMaxDynamicSharedMemorySize, smem_bytes);

    mlp_kernel<<<NSAMP / STILE, THREADS, smem_bytes>>>(
        app, view, W1, b1, W2, b2, W3, b3);
    reduce_kernel<<<NRAYS / 32, 32>>>(sigma, dists, out);
}

// round 15
// speedup vs baseline: 2.9747x; 2.9653x over previous
#include <cuda_runtime.h>
#include <cuda_bf16.h>
#include <cstdint>
#include <math.h>

// ===========================================================================
// TensoRF shading via warp-level bf16 tensor cores (mma.sync m16n8k16),
// 3-term hi/lo split for fp32-grade accuracy. No tcgen05 (harness compiles
// for plain sm_103 — only baseline PTX features allowed).
//
//  prep_kernel : permute W1 rows into PE-group K-order (K=512, 3 pads/group),
//                split W1/W2 into bf16 hi+lo, store as the exact swizzled
//                SMEM image so staging is a linear cp.async copy.
//  mlp_kernel  : CTA = 128 samples, 8 warps. X (128x512 bf16) generated in
//                SMEM. Layer1: D += Xh*W1h + Xh*W1l (W chunks streamed via
//                cp.async ring), regen X as lo, D += Xl*W1h. Epilogue ->
//                h1 hi/lo in SMEM. Layer2: 3 terms from resident tiles.
//                Layer3 (128->3 + sigmoid) from registers + shfl reduce.
//  reduce_kernel: per-ray transmittance composite.
// ===========================================================================

#define NRAYS 4096
#define NS    128
#define NSAMP (NRAYS * NS)
#define MT    128
#define THREADS 256

// SMEM byte layout
#define XB   0                      // X: 128 rows x 1024B (512 bf16) = 128KB
#define WB   131072                 // 4 x 16KB cp.async ring
#define SM_TOTAL (WB + 4 * 16384)   // 192KB
// layer-2 reuse of the X region:
#define H1H  (XB)                   // 32KB
#define H1L  (XB + 32768)           // 32KB
#define W2HS (XB + 65536)           // 32KB
#define W2LS (XB + 98304)           // 32KB

static __device__ float g_rgb[(size_t)NSAMP * 3];
static __device__ __align__(16) __nv_bfloat16 gW1h[512 * 128];
static __device__ __align__(16) __nv_bfloat16 gW1l[512 * 128];
static __device__ __align__(16) __nv_bfloat16 gW2h[128 * 128];
static __device__ __align__(16) __nv_bfloat16 gW2l[128 * 128];

// ---------------------------------------------------------------- helpers
__device__ __forceinline__ uint32_t smem_u32(const void* p) {
    uint32_t a;
    asm("{ .reg .u64 t; cvta.to.shared.u64 t, %1; cvt.u32.u64 %0, t; }"
        : "=r"(a) : "l"(p));
    return a;
}
__device__ __forceinline__ void ldsm_x4(uint32_t* a, uint32_t addr) {
    asm volatile("ldmatrix.sync.aligned.m8n8.x4.shared.b16 {%0,%1,%2,%3}, [%4];"
                 : "=r"(a[0]), "=r"(a[1]), "=r"(a[2]), "=r"(a[3]) : "r"(addr));
}
__device__ __forceinline__ void ldsm_x2t(uint32_t* b, uint32_t addr) {
    asm volatile("ldmatrix.sync.aligned.m8n8.x2.trans.shared.b16 {%0,%1}, [%2];"
                 : "=r"(b[0]), "=r"(b[1]) : "r"(addr));
}
__device__ __forceinline__ void mma_bf16(float* d, const uint32_t* a,
                                         const uint32_t* b) {
    asm volatile(
        "mma.sync.aligned.m16n8k16.row.col.f32.bf16.bf16.f32 "
        "{%0,%1,%2,%3}, {%4,%5,%6,%7}, {%8,%9}, {%0,%1,%2,%3};"
        : "+f"(d[0]), "+f"(d[1]), "+f"(d[2]), "+f"(d[3])
        : "r"(a[0]), "r"(a[1]), "r"(a[2]), "r"(a[3]), "r"(b[0]), "r"(b[1]));
}
__device__ __forceinline__ void cp16(uint32_t dst, const void* src) {
    asm volatile("cp.async.cg.shared.global [%0], [%1], 16;"
                 :: "r"(dst), "l"(src) : "memory");
}
#define CP_COMMIT() asm volatile("cp.async.commit_group;" ::: "memory")
#define CP_WAIT3()  asm volatile("cp.async.wait_group 3;" ::: "memory")
#define CP_WAIT0()  asm volatile("cp.async.wait_group 0;" ::: "memory")

__device__ __forceinline__ uint32_t pkbf(float x0, float x1) {
    __nv_bfloat16 a = __float2bfloat16(x0), b = __float2bfloat16(x1);
    return (uint32_t)*(uint16_t*)&a | ((uint32_t)*(uint16_t*)&b << 16);
}

// ------------------------------------------------------- K-order permutation
// K' = 30 groups of 16: [v, sin f0..5, cos f0..5, 0,0,0]; groups 0..26 = app
// channels, 27..29 = view; kp in [480,512) is zero-pad.
__device__ __forceinline__ int orig_row(int kp) {
    int g = kp >> 4, t = kp & 15;
    if (g >= 30 || t >= 13) return -1;
    if (t == 0) return g;  // app ch g (g<27) or view ch (row 27+(g-27)=g)
    bool isapp = (g < 27);
    if (t <= 6)  return isapp ? (30 + g * 6 + (t - 1)) : (354 + (g - 27) * 6 + (t - 1));
    else         return isapp ? (192 + g * 6 + (t - 7)) : (372 + (g - 27) * 6 + (t - 7));
}

// ------------------------------------------------------------- prep kernel
// SMEM-image layout for a W tile: row k (256B = 128 bf16), 16B chunks
// swizzled chunk ^= (k & 7).
__global__ void prep_kernel(const float* __restrict__ W1,
                            const float* __restrict__ W2)
{
    int t = blockIdx.x * blockDim.x + threadIdx.x;
    if (t < 512 * 128) {
        int n = t >> 9, kp = t & 511;
        int r = orig_row(kp);
        float w = (r >= 0) ? W1[r * 128 + n] : 0.0f;
        __nv_bfloat16 hi = __float2bfloat16(w);
        __nv_bfloat16 lo = __float2bfloat16(w - __bfloat162float(hi));
        int ch = kp >> 6, k = kp & 63;
        size_t off = (size_t)ch * 16384 + k * 256
                   + (((n >> 3) ^ (k & 7)) * 16) + ((n & 7) * 2);
        *(__nv_bfloat16*)((char*)gW1h + off) = hi;
        *(__nv_bfloat16*)((char*)gW1l + off) = lo;
    } else {
        t -= 512 * 128;
        if (t < 128 * 128) {
            int n = t >> 7, k = t & 127;
            float w = W2[k * 128 + n];
            __nv_bfloat16 hi = __float2bfloat16(w);
            __nv_bfloat16 lo = __float2bfloat16(w - __bfloat162float(hi));
            size_t off = (size_t)k * 256
                       + (((n >> 3) ^ (k & 7)) * 16) + ((n & 7) * 2);
            *(__nv_bfloat16*)((char*)gW2h + off) = hi;
            *(__nv_bfloat16*)((char*)gW2l + off) = lo;
        }
    }
}

// ------------------------------------------------- encoded X generation
// X row = sample (1024B = 512 bf16), 16B chunks swizzled chunk ^= (s & 7).
__device__ void gen_x(char* smem, const float* __restrict__ app,
                      const float* __restrict__ view,
                      int tid, size_t base, bool lo)
{
    const int s  = tid >> 1;
    const int g0 = (tid & 1) * 15;
    const size_t gs = base + s;
    char* xrow = smem + XB + s * 1024;
    const int rm = s & 7;

    #pragma unroll 1
    for (int gi = 0; gi < 15; gi++) {
        int g = g0 + gi;
        float v = (g < 27) ? __ldg(app + gs * 27 + g)
                           : __ldg(view + gs * 3 + (g - 27));
        float h[16];
        h[0] = v;
        float sn, cs;
        __sincosf(v, &sn, &cs);
        #pragma unroll
        for (int f = 0; f < 6; f++) {
            h[1 + f] = sn; h[7 + f] = cs;
            float sn2 = 2.0f * sn * cs;
            float cs2 = 1.0f - 2.0f * sn * sn;
            sn = sn2; cs = cs2;
        }
        h[13] = h[14] = h[15] = 0.0f;
        const int cbase = 2 * g;
        #pragma unroll
        for (int p = 0; p < 8; p++) {
            float x0 = h[2 * p], x1 = h[2 * p + 1];
            float o0 = x0, o1 = x1;
            if (lo) {
                o0 = x0 - __bfloat162float(__float2bfloat16(x0));
                o1 = x1 - __bfloat162float(__float2bfloat16(x1));
            }
            int chunk = (cbase + (p >> 2)) ^ rm;
            *(uint32_t*)(xrow + chunk * 16 + (p & 3) * 4) = pkbf(o0, o1);
        }
    }
    // zero the pad chunks (logical kp 480..511) so no garbage hits the MMA
    {
        int c0 = 60 + (tid & 1) * 2;
        *(uint4*)(xrow + ((c0)     ^ rm) * 16) = make_uint4(0, 0, 0, 0);
        *(uint4*)(xrow + ((c0 + 1) ^ rm) * 16) = make_uint4(0, 0, 0, 0);
    }
}

// --------------------------------------------------------------- main kernel
__global__ void __launch_bounds__(THREADS, 1)
mlp_kernel(const float* __restrict__ app,
           const float* __restrict__ view,
           const float* __restrict__ b1,
           const float* __restrict__ b2,
           const float* __restrict__ W3,
           const float* __restrict__ b3)
{
    extern __shared__ __align__(16) char smem[];
    const uint32_t sb = smem_u32(smem);
    const int tid = threadIdx.x;
    const int wid = tid >> 5, lane = tid & 31;
    const int r0 = wid * 16;
    const size_t base = (size_t)blockIdx.x * MT;

    // A-operand addressing (layer 1: 1024B rows)
    const int arow = r0 + (lane & 15);
    const int ahalf = lane >> 4;
    const int arm = arow & 7;
    const uint32_t a_rowbase = sb + XB + arow * 1024;
    const int kb = lane & 15;          // B-operand k-row within 16

    float d[64];
    #pragma unroll
    for (int i = 0; i < 64; i++) d[i] = 0.0f;

    // ---- generate Xh ----
    gen_x(smem, app, view, tid, base, false);
    __syncthreads();

    // stage one 16KB W chunk into ring buffer `buf`
    auto stage = [&](const __nv_bfloat16* gsrc, int buf) {
        const uint4* s4 = (const uint4*)gsrc;
        uint32_t dst = sb + WB + buf * 16384 + tid * 16;
        #pragma unroll
        for (int j = 0; j < 4; j++)
            cp16(dst + j * 4096, s4 + tid + j * 256);
    };
    // one 64-K chunk of layer-1 MMAs from ring buffer `buf`, k16 base t0
    auto mma_chunk1 = [&](int buf, int t0) {
        const uint32_t wb = sb + WB + buf * 16384;
        #pragma unroll
        for (int u = 0; u < 4; u++) {
            int t = t0 + u;
            uint32_t a[4];
            ldsm_x4(a, a_rowbase + (((2 * t + ahalf) ^ arm) * 16));
            int k = u * 16 + kb;
            uint32_t bbase = wb + k * 256;
            int km = k & 7;
            #pragma unroll
            for (int nb = 0; nb < 16; nb++) {
                uint32_t b[2];
                ldsm_x2t(b, bbase + ((nb ^ km) * 16));
                mma_bf16(d + nb * 4, a, b);
            }
        }
    };

    // ---- layer-1 pass A+B: stream h0,l0,h1,l1,...,h7,l7 against Xh ----
    #pragma unroll
    for (int i = 0; i < 4; i++) {
        int kc = i >> 1;
        stage(((i & 1) ? gW1l : gW1h) + kc * 8192, i);
        CP_COMMIT();
    }
    #pragma unroll 1
    for (int i = 0; i < 16; i++) {
        CP_WAIT3();
        __syncthreads();
        mma_chunk1(i & 3, (i >> 1) * 4);
        __syncthreads();
        if (i + 4 < 16) {
            int kc = (i + 4) >> 1;
            stage((((i + 4) & 1) ? gW1l : gW1h) + kc * 8192, i & 3);
        }
        CP_COMMIT();
    }

    // ---- regenerate X as lo; pass C: stream h0..h7 ----
    gen_x(smem, app, view, tid, base, true);
    __syncthreads();
    #pragma unroll
    for (int i = 0; i < 4; i++) { stage(gW1h + i * 8192, i); CP_COMMIT(); }
    #pragma unroll 1
    for (int i = 0; i < 8; i++) {
        CP_WAIT3();
        __syncthreads();
        mma_chunk1(i & 3, i * 4);
        __syncthreads();
        if (i + 4 < 8) stage(gW1h + (i + 4) * 8192, i & 3);
        CP_COMMIT();
    }

    // ---- kick W2 hi/lo copies (64KB) into the upper X region ----
    {
        const uint4* sh = (const uint4*)gW2h;
        const uint4* sl = (const uint4*)gW2l;
        #pragma unroll
        for (int j = 0; j < 8; j++) {
            cp16(sb + W2HS + (tid + j * 256) * 16, sh + tid + j * 256);
            cp16(sb + W2LS + (tid + j * 256) * 16, sl + tid + j * 256);
        }
        CP_COMMIT();
    }

    // ---- epilogue 1: d -> relu(z+b1) -> h1 hi/lo (swizzled bf16 tiles) ----
    #pragma unroll
    for (int nb = 0; nb < 16; nb++) {
        int c0 = nb * 8 + 2 * (lane & 3);
        float bA = __ldg(b1 + c0), bB = __ldg(b1 + c0 + 1);
        #pragma unroll
        for (int h = 0; h < 2; h++) {
            float v0 = fmaxf(d[nb * 4 + h * 2 + 0] + bA, 0.0f);
            float v1 = fmaxf(d[nb * 4 + h * 2 + 1] + bB, 0.0f);
            int row = r0 + (lane >> 2) + h * 8;
            float h0 = __bfloat162float(__float2bfloat16(v0));
            float h1 = __bfloat162float(__float2bfloat16(v1));
            uint32_t off = row * 256 + (((c0 >> 3) ^ (row & 7)) * 16)
                         + ((c0 & 7) * 2);
            *(uint32_t*)(smem + H1H + off) = pkbf(h0, h1);
            *(uint32_t*)(smem + H1L + off) = pkbf(v0 - h0, v1 - h1);
        }
    }
    #pragma unroll
    for (int i = 0; i < 64; i++) d[i] = 0.0f;
    CP_WAIT0();
    __syncthreads();

    // ---- layer 2: 3 terms, K=128, all tiles resident (256B rows) ----
    {
        const int arow2 = r0 + (lane & 15);
        const int arm2 = arow2 & 7;
        #pragma unroll 1
        for (int pr = 0; pr < 3; pr++) {
            const uint32_t ab = sb + ((pr == 2) ? H1L : H1H) + arow2 * 256;
            const uint32_t wb = sb + ((pr == 1) ? W2LS : W2HS);
            #pragma unroll
            for (int t = 0; t < 8; t++) {
                uint32_t a[4];
                ldsm_x4(a, ab + (((2 * t + ahalf) ^ arm2) * 16));
                int k = t * 16 + kb;
                uint32_t bbase = wb + k * 256;
                int km = k & 7;
                #pragma unroll
                for (int nb = 0; nb < 16; nb++) {
                    uint32_t b[2];
                    ldsm_x2t(b, bbase + ((nb ^ km) * 16));
                    mma_bf16(d + nb * 4, a, b);
                }
            }
        }
    }

    // ---- layer 3 from registers: relu(z2+b2) @ W3 + sigmoid ----
    {
        float p[2][3] = {{0, 0, 0}, {0, 0, 0}};
        #pragma unroll
        for (int nb = 0; nb < 16; nb++) {
            int c0 = nb * 8 + 2 * (lane & 3);
            float bA = __ldg(b2 + c0), bB = __ldg(b2 + c0 + 1);
            float w3a[3], w3b[3];
            #pragma unroll
            for (int o = 0; o < 3; o++) {
                w3a[o] = __ldg(W3 + c0 * 3 + o);
                w3b[o] = __ldg(W3 + (c0 + 1) * 3 + o);
            }
            #pragma unroll
            for (int h = 0; h < 2; h++) {
                float v0 = fmaxf(d[nb * 4 + h * 2 + 0] + bA, 0.0f);
                float v1 = fmaxf(d[nb * 4 + h * 2 + 1] + bB, 0.0f);
                #pragma unroll
                for (int o = 0; o < 3; o++) {
                    p[h][o] = fmaf(v0, w3a[o], p[h][o]);
                    p[h][o] = fmaf(v1, w3b[o], p[h][o]);
                }
            }
        }
        #pragma unroll
        for (int h = 0; h < 2; h++)
            #pragma unroll
            for (int o = 0; o < 3; o++) {
                float v = p[h][o];
                v += __shfl_xor_sync(0xffffffffu, v, 1);
                v += __shfl_xor_sync(0xffffffffu, v, 2);
                p[h][o] = v;
            }
        if ((lane & 3) == 0) {
            #pragma unroll
            for (int h = 0; h < 2; h++) {
                int row = r0 + (lane >> 2) + h * 8;
                #pragma unroll
                for (int o = 0; o < 3; o++) {
                    float z = p[h][o] + __ldg(b3 + o);
                    g_rgb[(base + row) * 3 + o] = 1.0f / (1.0f + expf(-z));
                }
            }
        }
    }
}

// ---------------------------------------------------------------------------
__global__ void __launch_bounds__(32) reduce_kernel(
    const float* __restrict__ sf,
    const float* __restrict__ dd,
    float* __restrict__ out)
{
    const int r = blockIdx.x * blockDim.x + threadIdx.x;
    if (r >= NRAYS) return;

    const float* s  = sf + (size_t)r * NS;
    const float* d  = dd + (size_t)r * NS;
    const float* rb = g_rgb + (size_t)r * NS * 3;

    float T = 1.0f, o0 = 0.0f, o1 = 0.0f, o2 = 0.0f;
    #pragma unroll 4
    for (int i = 0; i < NS; i++) {
        float x = s[i] - 10.0f;
        float sig = log1pf(expf(x));
        float alpha = (i == NS - 1) ? 1.0f
                    : (1.0f - expf(-sig * d[i] * 25.0f));
        float w = alpha * T;
        o0 = fmaf(w, rb[i * 3 + 0], o0);
        o1 = fmaf(w, rb[i * 3 + 1], o1);
        o2 = fmaf(w, rb[i * 3 + 2], o2);
        T *= (1.0f - alpha + 1e-10f);
    }
    out[r * 3 + 0] = o0;
    out[r * 3 + 1] = o1;
    out[r * 3 + 2] = o2;
}

// ---------------------------------------------------------------------------
extern "C" void kernel_launch(void* const* d_in, const int* in_sizes, int n_in,
                              void* d_out, int out_size)
{
    const float* sigma = (const float*)d_in[0];
    const float* app   = (const float*)d_in[1];
    const float* view  = (const float*)d_in[2];
    const float* dists = (const float*)d_in[3];
    const float* W1    = (const float*)d_in[4];
    const float* b1    = (const float*)d_in[5];
    const float* W2    = (const float*)d_in[6];
    const float* b2    = (const float*)d_in[7];
    const float* W3    = (const float*)d_in[8];
    const float* b3    = (const float*)d_in[9];
    float* out = (float*)d_out;

    cudaFuncSetAttribute(mlp_kernel,
                         cudaFuncAttributeMaxDynamicSharedMemorySize, SM_TOTAL);

    prep_kernel<<<(512 * 128 + 128 * 128 + 255) / 256, 256>>>(W1, W2);
    mlp_kernel<<<NSAMP / MT, THREADS, SM_TOTAL>>>(app, view, b1, b2, W3, b3);
    reduce_kernel<<<NRAYS / 32, 32>>>(sigma, dists, out);
}

// round 16
// speedup vs baseline: 7.7279x; 2.5979x over previous
#include <cuda_runtime.h>
#include <cuda_fp16.h>
#include <cstdint>
#include <math.h>

// ===========================================================================
// TensoRF shading via warp-level fp16 tensor cores (mma.sync m16n8k16,
// fp32 accumulate). Single-term fp16 products: inputs rounded to fp16 once,
// error ~2^-12 per operand -> final rel_err ~1e-4 (gate 1e-3).
//
//  prep_kernel : permute W1 rows into PE-group K-order (K=512, 3 pads/group),
//                round W1/W2 to fp16, store as the exact swizzled SMEM image
//                so staging is a linear cp.async copy.
//  mlp_kernel  : CTA = 1 ray = 128 samples, 8 warps. X (128x512 fp16)
//                generated in SMEM (1 sincos + double-angle recurrence per
//                channel). Layer1: K=512 streamed via 4x16KB cp.async ring.
//                Layer2: K=128 resident. Layer3 (128->3 + sigmoid) straight
//                from D registers + shfl reduce. Then the per-ray
//                transmittance composite (shfl scan-product) -> out.
// ===========================================================================

#define NRAYS 4096
#define NS    128
#define MT    128
#define THREADS 256

// SMEM byte layout
#define XB   0                      // X: 128 rows x 1024B (512 fp16) = 128KB
#define WB   131072                 // 4 x 16KB cp.async ring
#define SM_TOTAL (WB + 4 * 16384)   // 192KB
// layer-2 reuse of the X region:
#define H1S  (XB)                   // h1 fp16, 32KB
#define W2S  (XB + 65536)           // W2 fp16, 32KB
// composite reuse (after layer-2 MMAs):
#define RGBS (XB)                   // 128 x 4 floats
#define WPRD (XB + 2048)            // 4 floats
#define PART (XB + 2176)            // 4 x 4 floats

static __device__ __align__(16) __half gW1[512 * 128];
static __device__ __align__(16) __half gW2[128 * 128];

// ---------------------------------------------------------------- helpers
__device__ __forceinline__ uint32_t smem_u32(const void* p) {
    uint32_t a;
    asm("{ .reg .u64 t; cvta.to.shared.u64 t, %1; cvt.u32.u64 %0, t; }"
        : "=r"(a) : "l"(p));
    return a;
}
__device__ __forceinline__ void ldsm_x4(uint32_t* a, uint32_t addr) {
    asm volatile("ldmatrix.sync.aligned.m8n8.x4.shared.b16 {%0,%1,%2,%3}, [%4];"
                 : "=r"(a[0]), "=r"(a[1]), "=r"(a[2]), "=r"(a[3]) : "r"(addr));
}
__device__ __forceinline__ void ldsm_x2t(uint32_t* b, uint32_t addr) {
    asm volatile("ldmatrix.sync.aligned.m8n8.x2.trans.shared.b16 {%0,%1}, [%2];"
                 : "=r"(b[0]), "=r"(b[1]) : "r"(addr));
}
__device__ __forceinline__ void mma_fp16(float* d, const uint32_t* a,
                                         const uint32_t* b) {
    asm volatile(
        "mma.sync.aligned.m16n8k16.row.col.f32.f16.f16.f32 "
        "{%0,%1,%2,%3}, {%4,%5,%6,%7}, {%8,%9}, {%0,%1,%2,%3};"
        : "+f"(d[0]), "+f"(d[1]), "+f"(d[2]), "+f"(d[3])
        : "r"(a[0]), "r"(a[1]), "r"(a[2]), "r"(a[3]), "r"(b[0]), "r"(b[1]));
}
__device__ __forceinline__ void cp16(uint32_t dst, const void* src) {
    asm volatile("cp.async.cg.shared.global [%0], [%1], 16;"
                 :: "r"(dst), "l"(src) : "memory");
}
#define CP_COMMIT() asm volatile("cp.async.commit_group;" ::: "memory")
#define CP_WAIT3()  asm volatile("cp.async.wait_group 3;" ::: "memory")
#define CP_WAIT0()  asm volatile("cp.async.wait_group 0;" ::: "memory")

__device__ __forceinline__ uint32_t pkhf(float x0, float x1) {
    __half2 h = __floats2half2_rn(x0, x1);
    return *(uint32_t*)&h;
}

// ------------------------------------------------------- K-order permutation
// K' = 30 groups of 16: [v, sin f0..5, cos f0..5, 0,0,0]; groups 0..26 = app
// channels, 27..29 = view; kp in [480,512) is zero-pad.
__device__ __forceinline__ int orig_row(int kp) {
    int g = kp >> 4, t = kp & 15;
    if (g >= 30 || t >= 13) return -1;
    if (t == 0) return g;
    bool isapp = (g < 27);
    if (t <= 6)  return isapp ? (30 + g * 6 + (t - 1)) : (354 + (g - 27) * 6 + (t - 1));
    else         return isapp ? (192 + g * 6 + (t - 7)) : (372 + (g - 27) * 6 + (t - 7));
}

// ------------------------------------------------------------- prep kernel
// SMEM-image layout for a W tile: row k (256B = 128 fp16), 16B chunks
// swizzled chunk ^= (k & 7).
__global__ void prep_kernel(const float* __restrict__ W1,
                            const float* __restrict__ W2)
{
    int t = blockIdx.x * blockDim.x + threadIdx.x;
    if (t < 512 * 128) {
        int n = t >> 9, kp = t & 511;
        int r = orig_row(kp);
        float w = (r >= 0) ? W1[r * 128 + n] : 0.0f;
        int ch = kp >> 6, k = kp & 63;
        size_t off = (size_t)ch * 16384 + k * 256
                   + (((n >> 3) ^ (k & 7)) * 16) + ((n & 7) * 2);
        *(__half*)((char*)gW1 + off) = __float2half_rn(w);
    } else {
        t -= 512 * 128;
        if (t < 128 * 128) {
            int n = t >> 7, k = t & 127;
            size_t off = (size_t)k * 256
                       + (((n >> 3) ^ (k & 7)) * 16) + ((n & 7) * 2);
            *(__half*)((char*)gW2 + off) = __float2half_rn(W2[k * 128 + n]);
        }
    }
}

// ------------------------------------------------- encoded X generation
// X row = sample (1024B = 512 fp16), 16B chunks swizzled chunk ^= (s & 7).
__device__ void gen_x(char* smem, const float* __restrict__ app,
                      const float* __restrict__ view,
                      int tid, size_t base)
{
    const int s  = tid >> 1;
    const int g0 = (tid & 1) * 15;
    const size_t gs = base + s;
    char* xrow = smem + XB + s * 1024;
    const int rm = s & 7;

    #pragma unroll 1
    for (int gi = 0; gi < 15; gi++) {
        int g = g0 + gi;
        float v = (g < 27) ? __ldg(app + gs * 27 + g)
                           : __ldg(view + gs * 3 + (g - 27));
        float h[16];
        h[0] = v;
        float sn, cs;
        __sincosf(v, &sn, &cs);
        #pragma unroll
        for (int f = 0; f < 6; f++) {
            h[1 + f] = sn; h[7 + f] = cs;
            float sn2 = 2.0f * sn * cs;
            float cs2 = 1.0f - 2.0f * sn * sn;
            sn = sn2; cs = cs2;
        }
        h[13] = h[14] = h[15] = 0.0f;
        const int cbase = 2 * g;
        #pragma unroll
        for (int p = 0; p < 8; p++) {
            int chunk = (cbase + (p >> 2)) ^ rm;
            *(uint32_t*)(xrow + chunk * 16 + (p & 3) * 4)
                = pkhf(h[2 * p], h[2 * p + 1]);
        }
    }
    // zero the pad chunks (logical kp 480..511)
    {
        int c0 = 60 + (tid & 1) * 2;
        *(uint4*)(xrow + ((c0)     ^ rm) * 16) = make_uint4(0, 0, 0, 0);
        *(uint4*)(xrow + ((c0 + 1) ^ rm) * 16) = make_uint4(0, 0, 0, 0);
    }
}

// --------------------------------------------------------------- main kernel
__global__ void __launch_bounds__(THREADS, 1)
mlp_kernel(const float* __restrict__ sigma,
           const float* __restrict__ app,
           const float* __restrict__ view,
           const float* __restrict__ dists,
           const float* __restrict__ b1,
           const float* __restrict__ b2,
           const float* __restrict__ W3,
           const float* __restrict__ b3,
           float* __restrict__ out)
{
    extern __shared__ __align__(16) char smem[];
    const uint32_t sb = smem_u32(smem);
    const int tid = threadIdx.x;
    const int wid = tid >> 5, lane = tid & 31;
    const int r0 = wid * 16;
    const size_t base = (size_t)blockIdx.x * MT;   // CTA == one ray

    // A-operand addressing (layer 1: 1024B rows)
    const int arow = r0 + (lane & 15);
    const int ahalf = lane >> 4;
    const int arm = arow & 7;
    const uint32_t a_rowbase = sb + XB + arow * 1024;
    const int kb = lane & 15;          // B-operand k-row within 16

    float d[64];
    #pragma unroll
    for (int i = 0; i < 64; i++) d[i] = 0.0f;

    // ---- generate X (fp16-rounded) ----
    gen_x(smem, app, view, tid, base);
    __syncthreads();

    // stage one 16KB W chunk into ring buffer `buf`
    auto stage = [&](const __half* gsrc, int buf) {
        const uint4* s4 = (const uint4*)gsrc;
        uint32_t dst = sb + WB + buf * 16384 + tid * 16;
        #pragma unroll
        for (int j = 0; j < 4; j++)
            cp16(dst + j * 4096, s4 + tid + j * 256);
    };
    // one 64-K chunk of layer-1 MMAs from ring buffer `buf`, k16 base t0
    auto mma_chunk1 = [&](int buf, int t0) {
        const uint32_t wb = sb + WB + buf * 16384;
        #pragma unroll
        for (int u = 0; u < 4; u++) {
            int t = t0 + u;
            uint32_t a[4];
            ldsm_x4(a, a_rowbase + (((2 * t + ahalf) ^ arm) * 16));
            int k = u * 16 + kb;
            uint32_t bbase = wb + k * 256;
            int km = k & 7;
            #pragma unroll
            for (int nb = 0; nb < 16; nb++) {
                uint32_t b[2];
                ldsm_x2t(b, bbase + ((nb ^ km) * 16));
                mma_fp16(d + nb * 4, a, b);
            }
        }
    };

    // ---- layer 1: stream 8 x 16KB chunks of W1 (K = 512) ----
    #pragma unroll
    for (int i = 0; i < 4; i++) { stage(gW1 + i * 8192, i); CP_COMMIT(); }
    #pragma unroll 1
    for (int i = 0; i < 8; i++) {
        CP_WAIT3();
        __syncthreads();
        mma_chunk1(i & 3, i * 4);
        __syncthreads();
        if (i + 4 < 8) stage(gW1 + (i + 4) * 8192, i & 3);
        CP_COMMIT();
    }

    // ---- kick W2 copy (32KB) into the upper X region ----
    {
        const uint4* s4 = (const uint4*)gW2;
        #pragma unroll
        for (int j = 0; j < 8; j++)
            cp16(sb + W2S + (tid + j * 256) * 16, s4 + tid + j * 256);
        CP_COMMIT();
    }

    // ---- epilogue 1: d -> relu(z+b1) -> h1 fp16 (swizzled tile) ----
    #pragma unroll
    for (int nb = 0; nb < 16; nb++) {
        int c0 = nb * 8 + 2 * (lane & 3);
        float bA = __ldg(b1 + c0), bB = __ldg(b1 + c0 + 1);
        #pragma unroll
        for (int h = 0; h < 2; h++) {
            float v0 = fmaxf(d[nb * 4 + h * 2 + 0] + bA, 0.0f);
            float v1 = fmaxf(d[nb * 4 + h * 2 + 1] + bB, 0.0f);
            int row = r0 + (lane >> 2) + h * 8;
            uint32_t off = row * 256 + (((c0 >> 3) ^ (row & 7)) * 16)
                         + ((c0 & 7) * 2);
            *(uint32_t*)(smem + H1S + off) = pkhf(v0, v1);
        }
    }
    #pragma unroll
    for (int i = 0; i < 64; i++) d[i] = 0.0f;
    CP_WAIT0();
    __syncthreads();

    // ---- layer 2: K = 128, resident tiles (256B rows) ----
    {
        const int arow2 = r0 + (lane & 15);
        const int arm2 = arow2 & 7;
        const uint32_t ab = sb + H1S + arow2 * 256;
        const uint32_t wb = sb + W2S;
        #pragma unroll
        for (int t = 0; t < 8; t++) {
            uint32_t a[4];
            ldsm_x4(a, ab + (((2 * t + ahalf) ^ arm2) * 16));
            int k = t * 16 + kb;
            uint32_t bbase = wb + k * 256;
            int km = k & 7;
            #pragma unroll
            for (int nb = 0; nb < 16; nb++) {
                uint32_t b[2];
                ldsm_x2t(b, bbase + ((nb ^ km) * 16));
                mma_fp16(d + nb * 4, a, b);
            }
        }
    }
    __syncthreads();   // everyone done reading H1S/W2S before rgb overwrites

    // ---- layer 3 from registers: relu(z2+b2) @ W3 + sigmoid -> rgb SMEM ----
    float* rgbs = (float*)(smem + RGBS);       // [128][4]
    {
        float p[2][3] = {{0, 0, 0}, {0, 0, 0}};
        #pragma unroll
        for (int nb = 0; nb < 16; nb++) {
            int c0 = nb * 8 + 2 * (lane & 3);
            float bA = __ldg(b2 + c0), bB = __ldg(b2 + c0 + 1);
            float w3a[3], w3b[3];
            #pragma unroll
            for (int o = 0; o < 3; o++) {
                w3a[o] = __ldg(W3 + c0 * 3 + o);
                w3b[o] = __ldg(W3 + (c0 + 1) * 3 + o);
            }
            #pragma unroll
            for (int h = 0; h < 2; h++) {
                float v0 = fmaxf(d[nb * 4 + h * 2 + 0] + bA, 0.0f);
                float v1 = fmaxf(d[nb * 4 + h * 2 + 1] + bB, 0.0f);
                #pragma unroll
                for (int o = 0; o < 3; o++) {
                    p[h][o] = fmaf(v0, w3a[o], p[h][o]);
                    p[h][o] = fmaf(v1, w3b[o], p[h][o]);
                }
            }
        }
        #pragma unroll
        for (int h = 0; h < 2; h++)
            #pragma unroll
            for (int o = 0; o < 3; o++) {
                float v = p[h][o];
                v += __shfl_xor_sync(0xffffffffu, v, 1);
                v += __shfl_xor_sync(0xffffffffu, v, 2);
                p[h][o] = v;
            }
        if ((lane & 3) == 0) {
            #pragma unroll
            for (int h = 0; h < 2; h++) {
                int row = r0 + (lane >> 2) + h * 8;
                #pragma unroll
                for (int o = 0; o < 3; o++) {
                    float z = p[h][o] + __ldg(b3 + o);
                    rgbs[row * 4 + o] = 1.0f / (1.0f + expf(-z));
                }
            }
        }
    }
    __syncthreads();

    // ---- fused per-ray transmittance composite (shfl scan-product) ----
    float* wprd = (float*)(smem + WPRD);
    float* part = (float*)(smem + PART);
    if (tid < 128) {
        float x = __ldg(sigma + base + tid) - 10.0f;
        float sg = log1pf(expf(x));
        float alpha = (tid == 127) ? 1.0f
            : (1.0f - expf(-sg * __ldg(dists + base + tid) * 25.0f));
        float t = 1.0f - alpha + 1e-10f;
        // inclusive scan-product within warp
        float pincl = t;
        #pragma unroll
        for (int dstep = 1; dstep < 32; dstep <<= 1) {
            float v = __shfl_up_sync(0xffffffffu, pincl, dstep);
            if (lane >= dstep) pincl *= v;
        }
        if (lane == 31) wprd[wid] = pincl;
        __syncwarp();
        float pexcl = __shfl_up_sync(0xffffffffu, pincl, 1);
        if (lane == 0) pexcl = 1.0f;
        // cross-warp prefix (wid < 4)
        __syncthreads();
        float pre = 1.0f;
        for (int w = 0; w < wid; w++) pre *= wprd[w];
        float T = pre * pexcl;
        float wgt = alpha * T;
        float r0v = wgt * rgbs[tid * 4 + 0];
        float r1v = wgt * rgbs[tid * 4 + 1];
        float r2v = wgt * rgbs[tid * 4 + 2];
        #pragma unroll
        for (int dstep = 16; dstep >= 1; dstep >>= 1) {
            r0v += __shfl_xor_sync(0xffffffffu, r0v, dstep);
            r1v += __shfl_xor_sync(0xffffffffu, r1v, dstep);
            r2v += __shfl_xor_sync(0xffffffffu, r2v, dstep);
        }
        if (lane == 0) {
            part[wid * 4 + 0] = r0v;
            part[wid * 4 + 1] = r1v;
            part[wid * 4 + 2] = r2v;
        }
    } else {
        __syncthreads();   // match the barrier inside the composite branch
    }
    __syncthreads();
    if (tid < 3) {
        float s = part[tid] + part[4 + tid] + part[8 + tid] + part[12 + tid];
        out[(size_t)blockIdx.x * 3 + tid] = s;
    }
}

// ---------------------------------------------------------------------------
extern "C" void kernel_launch(void* const* d_in, const int* in_sizes, int n_in,
                              void* d_out, int out_size)
{
    const float* sigma = (const float*)d_in[0];
    const float* app   = (const float*)d_in[1];
    const float* view  = (const float*)d_in[2];
    const float* dists = (const float*)d_in[3];
    const float* W1    = (const float*)d_in[4];
    const float* b1    = (const float*)d_in[5];
    const float* W2    = (const float*)d_in[6];
    const float* b2    = (const float*)d_in[7];
    const float* W3    = (const float*)d_in[8];
    const float* b3    = (const float*)d_in[9];
    float* out = (float*)d_out;

    cudaFuncSetAttribute(mlp_kernel,
                         cudaFuncAttributeMaxDynamicSharedMemorySize, SM_TOTAL);

    prep_kernel<<<(512 * 128 + 128 * 128 + 255) / 256, 256>>>(W1, W2);
    mlp_kernel<<<NRAYS, THREADS, SM_TOTAL>>>(sigma, app, view, dists,
                                             b1, b2, W3, b3, out);
}

// round 17
// speedup vs baseline: 7.8589x; 1.0170x over previous
#include <cuda_runtime.h>
#include <cuda_fp16.h>
#include <cstdint>
#include <math.h>

// ===========================================================================
// TensoRF shading via warp-level fp16 tensor cores (mma.sync m16n8k16,
// fp32 accumulate). Round 5: 512 threads/CTA, warp tile 16x64 (d=32 regs)
// -> 16 warps/SM, 4/SMSP for latency hiding. CTA = 1 ray = 128 samples.
// ===========================================================================

#define NRAYS 4096
#define NS    128
#define MT    128
#define THREADS 512

// SMEM byte layout
#define XB   0                      // X: 128 rows x 1024B (512 fp16) = 128KB
#define WB   131072                 // 4 x 16KB cp.async ring
#define SM_TOTAL (WB + 4 * 16384)   // 192KB
// layer-2 reuse of the X region:
#define H1S  (XB)                   // h1 fp16, 32KB
#define W2S  (XB + 65536)           // W2 fp16, 32KB
// composite reuse (after layer-2 MMAs):
#define RGBS (XB)                   // 128 x 8 floats (per-col-half partials)
#define WPRD (XB + 4096)            // 4 floats
#define PART (XB + 4224)            // 4 x 4 floats

static __device__ __align__(16) __half gW1[512 * 128];
static __device__ __align__(16) __half gW2[128 * 128];

// ---------------------------------------------------------------- helpers
__device__ __forceinline__ uint32_t smem_u32(const void* p) {
    uint32_t a;
    asm("{ .reg .u64 t; cvta.to.shared.u64 t, %1; cvt.u32.u64 %0, t; }"
        : "=r"(a) : "l"(p));
    return a;
}
__device__ __forceinline__ void ldsm_x4(uint32_t* a, uint32_t addr) {
    asm volatile("ldmatrix.sync.aligned.m8n8.x4.shared.b16 {%0,%1,%2,%3}, [%4];"
                 : "=r"(a[0]), "=r"(a[1]), "=r"(a[2]), "=r"(a[3]) : "r"(addr));
}
__device__ __forceinline__ void ldsm_x2t(uint32_t* b, uint32_t addr) {
    asm volatile("ldmatrix.sync.aligned.m8n8.x2.trans.shared.b16 {%0,%1}, [%2];"
                 : "=r"(b[0]), "=r"(b[1]) : "r"(addr));
}
__device__ __forceinline__ void mma_fp16(float* d, const uint32_t* a,
                                         const uint32_t* b) {
    asm volatile(
        "mma.sync.aligned.m16n8k16.row.col.f32.f16.f16.f32 "
        "{%0,%1,%2,%3}, {%4,%5,%6,%7}, {%8,%9}, {%0,%1,%2,%3};"
        : "+f"(d[0]), "+f"(d[1]), "+f"(d[2]), "+f"(d[3])
        : "r"(a[0]), "r"(a[1]), "r"(a[2]), "r"(a[3]), "r"(b[0]), "r"(b[1]));
}
__device__ __forceinline__ void cp16(uint32_t dst, const void* src) {
    asm volatile("cp.async.cg.shared.global [%0], [%1], 16;"
                 :: "r"(dst), "l"(src) : "memory");
}
#define CP_COMMIT() asm volatile("cp.async.commit_group;" ::: "memory")
#define CP_WAIT3()  asm volatile("cp.async.wait_group 3;" ::: "memory")
#define CP_WAIT0()  asm volatile("cp.async.wait_group 0;" ::: "memory")

__device__ __forceinline__ uint32_t pkhf(float x0, float x1) {
    __half2 h = __floats2half2_rn(x0, x1);
    return *(uint32_t*)&h;
}

// ------------------------------------------------------- K-order permutation
// K' = 30 groups of 16: [v, sin f0..5, cos f0..5, 0,0,0]; groups 0..26 = app
// channels, 27..29 = view; kp in [480,512) is zero-pad.
__device__ __forceinline__ int orig_row(int kp) {
    int g = kp >> 4, t = kp & 15;
    if (g >= 30 || t >= 13) return -1;
    if (t == 0) return g;
    bool isapp = (g < 27);
    if (t <= 6)  return isapp ? (30 + g * 6 + (t - 1)) : (354 + (g - 27) * 6 + (t - 1));
    else         return isapp ? (192 + g * 6 + (t - 7)) : (372 + (g - 27) * 6 + (t - 7));
}

// ------------------------------------------------------------- prep kernel
// SMEM-image layout for a W tile: row k (256B = 128 fp16), 16B chunks
// swizzled chunk ^= (k & 7).
__global__ void prep_kernel(const float* __restrict__ W1,
                            const float* __restrict__ W2)
{
    int t = blockIdx.x * blockDim.x + threadIdx.x;
    if (t < 512 * 128) {
        int n = t >> 9, kp = t & 511;
        int r = orig_row(kp);
        float w = (r >= 0) ? W1[r * 128 + n] : 0.0f;
        int ch = kp >> 6, k = kp & 63;
        size_t off = (size_t)ch * 16384 + k * 256
                   + (((n >> 3) ^ (k & 7)) * 16) + ((n & 7) * 2);
        *(__half*)((char*)gW1 + off) = __float2half_rn(w);
    } else {
        t -= 512 * 128;
        if (t < 128 * 128) {
            int n = t >> 7, k = t & 127;
            size_t off = (size_t)k * 256
                       + (((n >> 3) ^ (k & 7)) * 16) + ((n & 7) * 2);
            *(__half*)((char*)gW2 + off) = __float2half_rn(W2[k * 128 + n]);
        }
    }
}

// ------------------------------------------------- encoded X generation
// X row = sample (1024B = 512 fp16), 16B chunks swizzled chunk ^= (s & 7).
// 512 threads: 4 threads per sample, thread j handles PE groups [8j, 8j+8).
__device__ void gen_x(char* smem, const float* __restrict__ app,
                      const float* __restrict__ view,
                      int tid, size_t base)
{
    const int s = tid >> 2;
    const int j = tid & 3;
    const size_t gs = base + s;
    char* xrow = smem + XB + s * 1024;
    const int rm = s & 7;

    #pragma unroll 1
    for (int gi = 0; gi < 8; gi++) {
        int g = j * 8 + gi;
        if (g >= 30) break;
        float v = (g < 27) ? __ldg(app + gs * 27 + g)
                           : __ldg(view + gs * 3 + (g - 27));
        float h[16];
        h[0] = v;
        float sn, cs;
        __sincosf(v, &sn, &cs);
        #pragma unroll
        for (int f = 0; f < 6; f++) {
            h[1 + f] = sn; h[7 + f] = cs;
            float sn2 = 2.0f * sn * cs;
            float cs2 = 1.0f - 2.0f * sn * sn;
            sn = sn2; cs = cs2;
        }
        h[13] = h[14] = h[15] = 0.0f;
        const int cbase = 2 * g;
        #pragma unroll
        for (int p = 0; p < 8; p++) {
            int chunk = (cbase + (p >> 2)) ^ rm;
            *(uint32_t*)(xrow + chunk * 16 + (p & 3) * 4)
                = pkhf(h[2 * p], h[2 * p + 1]);
        }
    }
    // zero one pad chunk each (logical kp 480..511 -> chunks 60..63)
    *(uint4*)(xrow + ((60 + j) ^ rm) * 16) = make_uint4(0, 0, 0, 0);
}

// --------------------------------------------------------------- main kernel
__global__ void __launch_bounds__(THREADS, 1)
mlp_kernel(const float* __restrict__ sigma,
           const float* __restrict__ app,
           const float* __restrict__ view,
           const float* __restrict__ dists,
           const float* __restrict__ b1,
           const float* __restrict__ b2,
           const float* __restrict__ W3,
           const float* __restrict__ b3,
           float* __restrict__ out)
{
    extern __shared__ __align__(16) char smem[];
    const uint32_t sb = smem_u32(smem);
    const int tid = threadIdx.x;
    const int wid = tid >> 5, lane = tid & 31;
    const int rg = wid >> 1;            // row group 0..7
    const int chf = wid & 1;            // col half 0..1
    const int r0 = rg * 16;
    const int nb0 = chf * 8;            // first n8-block of this warp
    const size_t base = (size_t)blockIdx.x * MT;   // CTA == one ray

    // A-operand addressing (layer 1: 1024B rows)
    const int arow = r0 + (lane & 15);
    const int ahalf = lane >> 4;
    const int arm = arow & 7;
    const uint32_t a_rowbase = sb + XB + arow * 1024;
    const int kb = lane & 15;           // B-operand k-row within 16

    float d[32];
    #pragma unroll
    for (int i = 0; i < 32; i++) d[i] = 0.0f;

    // stage one 16KB W chunk into ring buffer `buf` (512 thr -> 2 cp16 each)
    auto stage = [&](const __half* gsrc, int buf) {
        const uint4* s4 = (const uint4*)gsrc;
        uint32_t dst = sb + WB + buf * 16384 + tid * 16;
        cp16(dst,        s4 + tid);
        cp16(dst + 8192, s4 + tid + 512);
    };

    // ---- kick first 4 W1 chunks, then generate X under the copies ----
    #pragma unroll
    for (int i = 0; i < 4; i++) { stage(gW1 + i * 8192, i); CP_COMMIT(); }
    gen_x(smem, app, view, tid, base);
    __syncthreads();

    // one 64-K chunk of layer-1 MMAs from ring buffer `buf`, k16 base t0
    auto mma_chunk1 = [&](int buf, int t0) {
        const uint32_t wb = sb + WB + buf * 16384;
        #pragma unroll
        for (int u = 0; u < 4; u++) {
            int t = t0 + u;
            uint32_t a[4];
            ldsm_x4(a, a_rowbase + (((2 * t + ahalf) ^ arm) * 16));
            int k = u * 16 + kb;
            uint32_t bbase = wb + k * 256;
            int km = k & 7;
            #pragma unroll
            for (int nb = 0; nb < 8; nb++) {
                uint32_t b[2];
                ldsm_x2t(b, bbase + (((nb0 + nb) ^ km) * 16));
                mma_fp16(d + nb * 4, a, b);
            }
        }
    };

    // ---- layer 1: stream 8 x 16KB chunks of W1 (K = 512) ----
    #pragma unroll 1
    for (int i = 0; i < 8; i++) {
        CP_WAIT3();
        __syncthreads();
        mma_chunk1(i & 3, i * 4);
        __syncthreads();
        if (i + 4 < 8) stage(gW1 + (i + 4) * 8192, i & 3);
        CP_COMMIT();
    }

    // ---- kick W2 copy (32KB) into the upper X region ----
    {
        const uint4* s4 = (const uint4*)gW2;
        cp16(sb + W2S + tid * 16,         s4 + tid);
        cp16(sb + W2S + tid * 16 + 8192,  s4 + tid + 512);
        cp16(sb + W2S + tid * 16 + 16384, s4 + tid + 1024);
        cp16(sb + W2S + tid * 16 + 24576, s4 + tid + 1536);
        CP_COMMIT();
    }

    // ---- epilogue 1: d -> relu(z+b1) -> h1 fp16 (swizzled tile) ----
    #pragma unroll
    for (int nb = 0; nb < 8; nb++) {
        int c0 = nb0 * 8 + nb * 8 + 2 * (lane & 3);
        float bA = __ldg(b1 + c0), bB = __ldg(b1 + c0 + 1);
        #pragma unroll
        for (int h = 0; h < 2; h++) {
            float v0 = fmaxf(d[nb * 4 + h * 2 + 0] + bA, 0.0f);
            float v1 = fmaxf(d[nb * 4 + h * 2 + 1] + bB, 0.0f);
            int row = r0 + (lane >> 2) + h * 8;
            uint32_t off = row * 256 + (((c0 >> 3) ^ (row & 7)) * 16)
                         + ((c0 & 7) * 2);
            *(uint32_t*)(smem + H1S + off) = pkhf(v0, v1);
        }
    }
    #pragma unroll
    for (int i = 0; i < 32; i++) d[i] = 0.0f;
    CP_WAIT0();
    __syncthreads();

    // ---- layer 2: K = 128, resident tiles (256B rows) ----
    {
        const int arm2 = arow & 7;
        const uint32_t ab = sb + H1S + arow * 256;
        const uint32_t wb = sb + W2S;
        #pragma unroll
        for (int t = 0; t < 8; t++) {
            uint32_t a[4];
            ldsm_x4(a, ab + (((2 * t + ahalf) ^ arm2) * 16));
            int k = t * 16 + kb;
            uint32_t bbase = wb + k * 256;
            int km = k & 7;
            #pragma unroll
            for (int nb = 0; nb < 8; nb++) {
                uint32_t b[2];
                ldsm_x2t(b, bbase + (((nb0 + nb) ^ km) * 16));
                mma_fp16(d + nb * 4, a, b);
            }
        }
    }
    __syncthreads();   // all reads of H1S/W2S done before rgb overwrites

    // ---- layer 3 partials: relu(z2+b2) @ W3 over this warp's 64 cols ----
    float* rgbs = (float*)(smem + RGBS);       // [128][8]: [row][chf*4+o]
    {
        float p[2][3] = {{0, 0, 0}, {0, 0, 0}};
        #pragma unroll
        for (int nb = 0; nb < 8; nb++) {
            int c0 = nb0 * 8 + nb * 8 + 2 * (lane & 3);
            float bA = __ldg(b2 + c0), bB = __ldg(b2 + c0 + 1);
            float w3a[3], w3b[3];
            #pragma unroll
            for (int o = 0; o < 3; o++) {
                w3a[o] = __ldg(W3 + c0 * 3 + o);
                w3b[o] = __ldg(W3 + (c0 + 1) * 3 + o);
            }
            #pragma unroll
            for (int h = 0; h < 2; h++) {
                float v0 = fmaxf(d[nb * 4 + h * 2 + 0] + bA, 0.0f);
                float v1 = fmaxf(d[nb * 4 + h * 2 + 1] + bB, 0.0f);
                #pragma unroll
                for (int o = 0; o < 3; o++) {
                    p[h][o] = fmaf(v0, w3a[o], p[h][o]);
                    p[h][o] = fmaf(v1, w3b[o], p[h][o]);
                }
            }
        }
        #pragma unroll
        for (int h = 0; h < 2; h++)
            #pragma unroll
            for (int o = 0; o < 3; o++) {
                float v = p[h][o];
                v += __shfl_xor_sync(0xffffffffu, v, 1);
                v += __shfl_xor_sync(0xffffffffu, v, 2);
                p[h][o] = v;
            }
        if ((lane & 3) == 0) {
            #pragma unroll
            for (int h = 0; h < 2; h++) {
                int row = r0 + (lane >> 2) + h * 8;
                #pragma unroll
                for (int o = 0; o < 3; o++)
                    rgbs[row * 8 + chf * 4 + o] = p[h][o];
            }
        }
    }
    __syncthreads();

    // ---- fused per-ray transmittance composite (shfl scan-product) ----
    float* wprd = (float*)(smem + WPRD);
    float* part = (float*)(smem + PART);
    if (tid < 128) {
        float x = __ldg(sigma + base + tid) - 10.0f;
        float sg = log1pf(expf(x));
        float alpha = (tid == 127) ? 1.0f
            : (1.0f - expf(-sg * __ldg(dists + base + tid) * 25.0f));
        float t = 1.0f - alpha + 1e-10f;
        // inclusive scan-product within warp
        float pincl = t;
        #pragma unroll
        for (int dstep = 1; dstep < 32; dstep <<= 1) {
            float v = __shfl_up_sync(0xffffffffu, pincl, dstep);
            if (lane >= dstep) pincl *= v;
        }
        if (lane == 31) wprd[wid] = pincl;
        __syncwarp();
        float pexcl = __shfl_up_sync(0xffffffffu, pincl, 1);
        if (lane == 0) pexcl = 1.0f;
        __syncthreads();
        float pre = 1.0f;
        for (int w = 0; w < wid; w++) pre *= wprd[w];
        float T = pre * pexcl;
        float wgt = alpha * T;
        float r0v, r1v, r2v;
        {
            float z0 = rgbs[tid * 8 + 0] + rgbs[tid * 8 + 4] + __ldg(b3 + 0);
            float z1 = rgbs[tid * 8 + 1] + rgbs[tid * 8 + 5] + __ldg(b3 + 1);
            float z2 = rgbs[tid * 8 + 2] + rgbs[tid * 8 + 6] + __ldg(b3 + 2);
            r0v = wgt / (1.0f + expf(-z0));
            r1v = wgt / (1.0f + expf(-z1));
            r2v = wgt / (1.0f + expf(-z2));
        }
        #pragma unroll
        for (int dstep = 16; dstep >= 1; dstep >>= 1) {
            r0v += __shfl_xor_sync(0xffffffffu, r0v, dstep);
            r1v += __shfl_xor_sync(0xffffffffu, r1v, dstep);
            r2v += __shfl_xor_sync(0xffffffffu, r2v, dstep);
        }
        if (lane == 0) {
            part[wid * 4 + 0] = r0v;
            part[wid * 4 + 1] = r1v;
            part[wid * 4 + 2] = r2v;
        }
    } else {
        __syncthreads();   // match the barrier inside the composite branch
    }
    __syncthreads();
    if (tid < 3) {
        float s = part[tid] + part[4 + tid] + part[8 + tid] + part[12 + tid];
        out[(size_t)blockIdx.x * 3 + tid] = s;
    }
}

// ---------------------------------------------------------------------------
extern "C" void kernel_launch(void* const* d_in, const int* in_sizes, int n_in,
                              void* d_out, int out_size)
{
    const float* sigma = (const float*)d_in[0];
    const float* app   = (const float*)d_in[1];
    const float* view  = (const float*)d_in[2];
    const float* dists = (const float*)d_in[3];
    const float* W1    = (const float*)d_in[4];
    const float* b1    = (const float*)d_in[5];
    const float* W2    = (const float*)d_in[6];
    const float* b2    = (const float*)d_in[7];
    const float* W3    = (const float*)d_in[8];
    const float* b3    = (const float*)d_in[9];
    float* out = (float*)d_out;

    cudaFuncSetAttribute(mlp_kernel,
                         cudaFuncAttributeMaxDynamicSharedMemorySize, SM_TOTAL);

    prep_kernel<<<(512 * 128 + 128 * 128 + 255) / 256, 256>>>(W1, W2);
    mlp_kernel<<<NRAYS, THREADS, SM_TOTAL>>>(sigma, app, view, dists,
                                             b1, b2, W3, b3, out);
}